// round 10
// baseline (speedup 1.0000x reference)
#include <cuda_runtime.h>
#include <cuda_fp16.h>
#include <math.h>
#include <stdint.h>

#define NPOS    80
#define HID     128
#define GRID    256
#define THREADS 512
#define TILE    32      // rows per CTA (B = 8192 = 256*32)

// smem: planes [0,16384) floats (64KB, aliased by msg bytes in gather);
//       hA [16384,20480); hB [20480,24576)
#define SMEM_FLOATS 24576
#define SMEM_BYTES  (SMEM_FLOATS * 4)

// ---- device scratch ----
__device__ __half    g_W1h[NPOS * 256 * HID];   // 5.25 MB fp16 W1
__device__ float     g_Wp[3 * 4096 * 4];        // pre-paired W2/W3/W4
__device__ int       g_msg_is64;
__device__ unsigned  g_bar1;                    // zero-init; reset each launch
__device__ unsigned  g_bar2;

__device__ __forceinline__ float elu1(float x) {
    return x > 0.0f ? x : expm1f(x);
}

// ---- f32x2 packed helpers ----
__device__ __forceinline__ unsigned long long pk2(float lo, float hi) {
    unsigned long long r;
    asm("mov.b64 %0, {%1, %2};" : "=l"(r) : "f"(lo), "f"(hi));
    return r;
}
__device__ __forceinline__ void upk2(unsigned long long v, float& lo, float& hi) {
    asm("mov.b64 {%0, %1}, %2;" : "=f"(lo), "=f"(hi) : "l"(v));
}
__device__ __forceinline__ void fma2(unsigned long long& d,
                                     unsigned long long a, unsigned long long b) {
    asm("fma.rn.f32x2 %0, %1, %2, %0;" : "+l"(d) : "l"(a), "l"(b));
}
__device__ __forceinline__ void add2(unsigned long long& d, unsigned long long a) {
    asm("add.rn.f32x2 %0, %0, %1;" : "+l"(d) : "l"(a));
}
__device__ __forceinline__ unsigned long long h2f2(unsigned u) {
    float2 f = __half22float2(*(const __half2*)&u);
    return *(unsigned long long*)&f;
}

__global__ __launch_bounds__(THREADS, 2)
void mega_kernel(const int* __restrict__ msg,
                 const float* __restrict__ W1, const float* __restrict__ b1,
                 const float* __restrict__ W2, const float* __restrict__ b2,
                 const float* __restrict__ W3, const float* __restrict__ b3,
                 const float* __restrict__ W4, const float* __restrict__ b4,
                 float* __restrict__ out, int B)
{
    extern __shared__ float smem[];
    float4*     plane4 = (float4*)smem;
    ulonglong2* planeU = (ulonglong2*)smem;
    float4*     hA4    = (float4*)(smem + 16384);
    float4*     hB4    = (float4*)(smem + 16384 + TILE * HID);
    unsigned char* msg_sh = (unsigned char*)smem;      // 2560B, aliases planes

    __shared__ int s_flag;

    const int t  = threadIdx.x;
    const int bx = blockIdx.x;
    if (t == 0) s_flag = 0;
    __syncthreads();

    // ================= Phase A: convert + pair + detect =================
    {
        const int base = bx * THREADS + t;             // 0..131071
        #pragma unroll
        for (int j = 0; j < 5; j++) {
            int i = base + j * (GRID * THREADS);
            float4 v = __ldg(&((const float4*)W1)[i]);
            __half2 h0 = __floats2half2_rn(v.x, v.y);
            __half2 h1 = __floats2half2_rn(v.z, v.w);
            uint2 o;
            o.x = *(unsigned*)&h0;
            o.y = *(unsigned*)&h1;
            ((uint2*)g_W1h)[i] = o;
        }
    }
    if (bx < 12) {
        int task  = bx * THREADS + t;                  // 0..6143
        int layer = task >> 11;
        int i     = task & 2047;
        int k2 = i >> 5;
        int j  = i & 31;
        const float* Wsrc = (layer == 0) ? W2 : (layer == 1) ? W3 : W4;
        float4 a = __ldg(&((const float4*)Wsrc)[(2 * k2) * 32 + j]);
        float4 b = __ldg(&((const float4*)Wsrc)[(2 * k2 + 1) * 32 + j]);
        float4 pA; pA.x = a.x; pA.y = b.x; pA.z = a.y; pA.w = b.y;
        float4 pB; pB.x = a.z; pB.y = b.z; pB.z = a.w; pB.w = b.w;
        ((float4*)g_Wp)[layer * 4096 + i]        = pA;
        ((float4*)g_Wp)[layer * 4096 + 2048 + i] = pB;
    }
    if (bx == GRID - 1 && t < 256) {                   // int64 detect
        int v = 0;
        #pragma unroll
        for (int j = 0; j < 8; j++) v |= __ldg(&msg[2 * (t + j * 256) + 1]);
        if (v) atomicOr(&s_flag, 1);
    }
    __syncthreads();
    if (bx == GRID - 1 && t == 0) g_msg_is64 = (s_flag == 0) ? 1 : 0;

    // ================= device-wide barrier =================
    __threadfence();
    __syncthreads();
    if (t == 0) {
        atomicAdd(&g_bar1, 1u);
        while (atomicAdd(&g_bar1, 0u) < GRID) __nanosleep(64);
        __threadfence();
    }
    __syncthreads();

    // ================= Phase B: gather into smem hA =================
    const int row0 = bx * TILE;
    const int is64 = g_msg_is64;

    for (int idx = t; idx < TILE * NPOS; idx += THREADS) {
        int r = idx / NPOS;
        int p = idx - r * NPOS;
        int row = row0 + r;
        int c = 0;
        if (row < B) {
            int gi = row * NPOS + p;
            c = is64 ? __ldg(&msg[2 * gi]) : __ldg(&msg[gi]);
        }
        msg_sh[idx] = (unsigned char)c;                // [r][p], stride 80
    }
    __syncthreads();

    {
        const int lane = t & 31;
        const int w    = t >> 5;                       // 0..15
        const int hsel = lane >> 4;                    // row A / row B
        const int colg = lane & 15;                    // 16B group (8 hid cols)
        const int rowL = w * 2 + hsel;                 // 0..31

        unsigned long long acc[4];
        {
            float4 b0 = __ldg(&((const float4*)b1)[colg * 2]);
            float4 b1v = __ldg(&((const float4*)b1)[colg * 2 + 1]);
            acc[0] = pk2(b0.x, b0.y);
            acc[1] = pk2(b0.z, b0.w);
            acc[2] = pk2(b1v.x, b1v.y);
            acc[3] = pk2(b1v.z, b1v.w);
        }

        const uint4* Wb = (const uint4*)g_W1h + colg;
        const unsigned* mrow = (const unsigned*)(msg_sh + rowL * NPOS);

        #pragma unroll 4
        for (int p4 = 0; p4 < NPOS / 4; p4++) {
            unsigned c4 = mrow[p4];
            #pragma unroll
            for (int i = 0; i < 4; i++) {
                int c = (c4 >> (8 * i)) & 255;
                int p = p4 * 4 + i;
                uint4 u = __ldg(Wb + (((p << 8) + c) << 4));
                add2(acc[0], h2f2(u.x));
                add2(acc[1], h2f2(u.y));
                add2(acc[2], h2f2(u.z));
                add2(acc[3], h2f2(u.w));
            }
        }
        __syncthreads();   // all msg_sh reads done before planes overwrite it

        float4 v0, v1; float lo, hi;
        upk2(acc[0], lo, hi); v0.x = elu1(lo); v0.y = elu1(hi);
        upk2(acc[1], lo, hi); v0.z = elu1(lo); v0.w = elu1(hi);
        upk2(acc[2], lo, hi); v1.x = elu1(lo); v1.y = elu1(hi);
        upk2(acc[3], lo, hi); v1.z = elu1(lo); v1.w = elu1(hi);
        hA4[rowL * 32 + colg * 2]     = v0;
        hA4[rowL * 32 + colg * 2 + 1] = v1;
    }
    __syncthreads();

    // ================= Phase C: 3 dense layers =================
    const int j4 = t & 31;
    const int r0 = (t >> 5) * 2;      // 16 warps x 2 rows = 32

    const float* bg[3] = {b2, b3, b4};

    #pragma unroll 1
    for (int layer = 0; layer < 3; layer++) {
        const float4* hin  = (layer == 1) ? hB4 : hA4;
        float4*       hout = (layer == 1) ? hA4 : hB4;
        const bool    last = (layer == 2);

        const float4* Wg4 = (const float4*)g_Wp + layer * 4096;
        #pragma unroll 2
        for (int i = t; i < 4096; i += THREADS) plane4[i] = __ldg(&Wg4[i]);
        __syncthreads();

        unsigned long long a[2][4];
        {
            float4 bias = __ldg(&((const float4*)bg[layer])[j4]);
            #pragma unroll
            for (int r = 0; r < 2; r++) {
                a[r][0] = pk2(bias.x, 0.0f);
                a[r][1] = pk2(bias.y, 0.0f);
                a[r][2] = pk2(bias.z, 0.0f);
                a[r][3] = pk2(bias.w, 0.0f);
            }
        }

        #pragma unroll 4
        for (int k4 = 0; k4 < 32; k4++) {
            int k2 = 2 * k4;
            ulonglong2 wA0 = planeU[k2 * 32 + j4];
            ulonglong2 wB0 = planeU[2048 + k2 * 32 + j4];
            ulonglong2 wA1 = planeU[(k2 + 1) * 32 + j4];
            ulonglong2 wB1 = planeU[2048 + (k2 + 1) * 32 + j4];
            #pragma unroll
            for (int r = 0; r < 2; r++) {
                ulonglong2 hv = *(const ulonglong2*)&hin[(r0 + r) * 32 + k4];
                fma2(a[r][0], hv.x, wA0.x);
                fma2(a[r][1], hv.x, wA0.y);
                fma2(a[r][2], hv.x, wB0.x);
                fma2(a[r][3], hv.x, wB0.y);
                fma2(a[r][0], hv.y, wA1.x);
                fma2(a[r][1], hv.y, wA1.y);
                fma2(a[r][2], hv.y, wB1.x);
                fma2(a[r][3], hv.y, wB1.y);
            }
        }

        if (!last) {
            #pragma unroll
            for (int r = 0; r < 2; r++) {
                float4 v; float lo, hi;
                upk2(a[r][0], lo, hi); v.x = elu1(lo + hi);
                upk2(a[r][1], lo, hi); v.y = elu1(lo + hi);
                upk2(a[r][2], lo, hi); v.z = elu1(lo + hi);
                upk2(a[r][3], lo, hi); v.w = elu1(lo + hi);
                hout[(r0 + r) * 32 + j4] = v;
            }
            __syncthreads();
        } else {
            #pragma unroll
            for (int r = 0; r < 2; r++) {
                int row = row0 + r0 + r;
                if (row < B) {
                    float4 v; float lo, hi;
                    upk2(a[r][0], lo, hi); v.x = elu1(lo + hi);
                    upk2(a[r][1], lo, hi); v.y = elu1(lo + hi);
                    upk2(a[r][2], lo, hi); v.z = elu1(lo + hi);
                    upk2(a[r][3], lo, hi); v.w = elu1(lo + hi);
                    ((float4*)out)[row * 32 + j4] = v;
                }
            }
        }
    }

    // ---- replay-safe counter reset (last CTA through) ----
    if (t == 0) {
        unsigned d = atomicAdd(&g_bar2, 1u);
        if (d == GRID - 1) {
            atomicExch(&g_bar1, 0u);
            atomicExch(&g_bar2, 0u);
        }
    }
}

extern "C" void kernel_launch(void* const* d_in, const int* in_sizes, int n_in,
                              void* d_out, int out_size)
{
    const int*   msg = (const int*)  d_in[0];
    const float* W1  = (const float*)d_in[1];
    const float* b1  = (const float*)d_in[2];
    const float* W2  = (const float*)d_in[3];
    const float* b2  = (const float*)d_in[4];
    const float* W3  = (const float*)d_in[5];
    const float* b3  = (const float*)d_in[6];
    const float* W4  = (const float*)d_in[7];
    const float* b4  = (const float*)d_in[8];
    float* out = (float*)d_out;

    const int B = in_sizes[0] / NPOS;   // 8192

    cudaFuncSetAttribute(mega_kernel,
                         cudaFuncAttributeMaxDynamicSharedMemorySize, SMEM_BYTES);

    mega_kernel<<<GRID, THREADS, SMEM_BYTES>>>(msg, W1, b1, W2, b2, W3, b3,
                                               W4, b4, out, B);
}